// round 1
// baseline (speedup 1.0000x reference)
#include <cuda_runtime.h>
#include <cstdint>

#define NUM_A 98304
#define NUM_T 1024
#define NCLS  21

// ---------------- device-global scratch (no allocations allowed) -------------
__device__ unsigned long long g_tkey[NUM_T]; // per-target: (iou_bits<<32)|(~anchor)
__device__ double g_cls_sum;
__device__ double g_reg_sum;
__device__ int    g_npos;

// ---------------- init -------------------------------------------------------
__global__ void init_kernel() {
    int i = blockIdx.x * blockDim.x + threadIdx.x;
    if (i < NUM_T) g_tkey[i] = 0ULL;
    if (i == 0) { g_cls_sum = 0.0; g_reg_sum = 0.0; g_npos = 0; }
}

// ---------------- match + classification focal loss --------------------------
__global__ void __launch_bounds__(256) match_cls_kernel(
    const float* __restrict__ cls_preds,   // [A, 21]
    const float* __restrict__ anchors,     // [A, 4]
    const float* __restrict__ tboxes,      // [T, 4]
    const int*   __restrict__ tlabels)     // [T]
{
    __shared__ float4 s_tb[NUM_T];
    __shared__ float  s_ta[NUM_T];
    __shared__ int    s_tl[NUM_T];

    const int tid = threadIdx.x;
    for (int i = tid; i < NUM_T; i += 256) {
        float4 b = ((const float4*)tboxes)[i];
        s_tb[i] = b;
        s_ta[i] = (b.z - b.x) * (b.w - b.y);
        s_tl[i] = tlabels[i];
    }
    __syncthreads();

    const int a = blockIdx.x * 256 + tid;
    const float4 ab = ((const float4*)anchors)[a];
    const float area_a = (ab.z - ab.x) * (ab.w - ab.y);

    // anchor-side running best: compare iou via cross-multiplication
    float best_i = -1.0f, best_u = 1.0f;
    int   best_t = 0;

    #pragma unroll 4
    for (int t = 0; t < NUM_T; ++t) {
        float4 tb = s_tb[t];
        float lx = fmaxf(ab.x, tb.x);
        float ly = fmaxf(ab.y, tb.y);
        float rx = fminf(ab.z, tb.z);
        float ry = fminf(ab.w, tb.w);
        float w  = fmaxf(rx - lx, 0.0f);
        float h  = fmaxf(ry - ly, 0.0f);
        float inter = w * h;
        float uni   = area_a + s_ta[t] - inter;
        // strict > keeps first (lowest t) among exact ties == argmax semantics
        if (inter * best_u > best_i * uni) {
            best_i = inter; best_u = uni; best_t = t;
        }
        // target-side candidates: only iou > 0.45 can matter (mask threshold 0.5)
        if (inter > 0.45f * uni) {
            float iou = __fdividef(inter, uni);
            unsigned long long key =
                ((unsigned long long)__float_as_uint(iou) << 32)
                | (unsigned long long)(0xFFFFFFFFu - (unsigned)a);
            atomicMax(&g_tkey[t], key);
        }
    }

    const bool pos = (best_i >= 0.5f * best_u);
    const int  label = s_tl[best_t];

    // focal loss over this anchor's 21 logits
    float lsum = 0.0f;
    const float* lg = cls_preds + (size_t)a * NCLS;
    #pragma unroll
    for (int c = 0; c < NCLS; ++c) {
        float x = lg[c];
        bool  ypos = pos && (c == label);
        float ax = fabsf(x);
        float ce = fmaxf(x, 0.0f) - (ypos ? x : 0.0f) + log1pf(expf(-ax));
        float p  = 1.0f / (1.0f + expf(-x));
        float pt = ypos ? p : (1.0f - p);
        float at = ypos ? 0.25f : 0.75f;
        float om = 1.0f - pt;
        lsum += at * om * om * ce;
    }

    // block reduction (8 warps)
    int np = pos ? 1 : 0;
    #pragma unroll
    for (int o = 16; o > 0; o >>= 1) {
        lsum += __shfl_down_sync(0xFFFFFFFFu, lsum, o);
        np   += __shfl_down_sync(0xFFFFFFFFu, np,   o);
    }
    __shared__ float rs[8];
    __shared__ int   ri[8];
    int lane = tid & 31, wid = tid >> 5;
    if (lane == 0) { rs[wid] = lsum; ri[wid] = np; }
    __syncthreads();
    if (tid == 0) {
        float bs = 0.0f; int bn = 0;
        #pragma unroll
        for (int i = 0; i < 8; ++i) { bs += rs[i]; bn += ri[i]; }
        atomicAdd(&g_cls_sum, (double)bs);
        atomicAdd(&g_npos, bn);
    }
}

// ---------------- regression loss + final combine ----------------------------
__device__ __forceinline__ float sl1(float d) {
    float ad = fabsf(d);
    return (ad < 1.0f) ? 0.5f * d * d : ad - 0.5f;
}

__global__ void __launch_bounds__(1024) reg_final_kernel(
    const float* __restrict__ boxes_preds, // [A,4]
    const float* __restrict__ anchors,     // [A,4]
    const float* __restrict__ tboxes,      // [T,4]
    float* __restrict__ out)
{
    const int t = threadIdx.x;
    float loss = 0.0f;
    int   match = 0;

    unsigned long long key = g_tkey[t];
    float iou = __uint_as_float((unsigned)(key >> 32));
    if (iou >= 0.5f) {
        match = 1;
        unsigned aidx = 0xFFFFFFFFu - (unsigned)(key & 0xFFFFFFFFull);
        float4 ab = ((const float4*)anchors)[aidx];
        float4 tb = ((const float4*)tboxes)[t];
        float4 pr = ((const float4*)boxes_preds)[aidx];
        float bw = tb.z - tb.x, bh = tb.w - tb.y;
        float bcx = tb.x + 0.5f * bw, bcy = tb.y + 0.5f * bh;
        float aw = ab.z - ab.x, ah = ab.w - ab.y;
        float acx = ab.x + 0.5f * aw, acy = ab.y + 0.5f * ah;
        float tx = (bcx - acx) / aw;
        float ty = (bcy - acy) / ah;
        float tw = logf(fmaxf(bw, 1e-8f) / aw);
        float th = logf(fmaxf(bh, 1e-8f) / ah);
        loss = sl1(pr.x - tx) + sl1(pr.y - ty) + sl1(pr.z - tw) + sl1(pr.w - th);
    }

    // block reduce (32 warps)
    #pragma unroll
    for (int o = 16; o > 0; o >>= 1) {
        loss  += __shfl_down_sync(0xFFFFFFFFu, loss,  o);
        match += __shfl_down_sync(0xFFFFFFFFu, match, o);
    }
    __shared__ float rs[32];
    __shared__ int   rm[32];
    int lane = t & 31, wid = t >> 5;
    if (lane == 0) { rs[wid] = loss; rm[wid] = match; }
    __syncthreads();
    if (t == 0) {
        double total = 0.0; int nm = 0;
        #pragma unroll
        for (int i = 0; i < 32; ++i) { total += (double)rs[i]; nm += rm[i]; }
        double n_match = (nm > 0) ? (double)nm : 1.0;
        double cls = g_cls_sum / (double)g_npos;
        double reg = total / (n_match * 4.0);
        out[0] = (float)(cls + reg);
        out[1] = (float)cls;
        out[2] = (float)reg;
    }
}

// ---------------- launch -----------------------------------------------------
extern "C" void kernel_launch(void* const* d_in, const int* in_sizes, int n_in,
                              void* d_out, int out_size) {
    const float* cls_preds = (const float*)d_in[0];
    const float* box_preds = (const float*)d_in[1];
    const float* anchors   = (const float*)d_in[2];
    const float* tboxes    = (const float*)d_in[3];
    const int*   tlabels   = (const int*)d_in[4];
    float* out = (float*)d_out;

    init_kernel<<<1, 1024>>>();
    match_cls_kernel<<<NUM_A / 256, 256>>>(cls_preds, anchors, tboxes, tlabels);
    reg_final_kernel<<<1, 1024>>>(box_preds, anchors, tboxes, out);
}

// round 2
// speedup vs baseline: 1.2432x; 1.2432x over previous
#include <cuda_runtime.h>
#include <cstdint>

#define NUM_A  98304
#define NUM_T  1024
#define NCLS   21
#define CHUNK  128        // targets per chunk-block
#define NCHUNK 8          // NUM_T / CHUNK
#define APT    2          // anchors per thread
#define BLK    256

typedef unsigned long long ull;

// ---------------- device-global scratch (no allocations allowed) -------------
__device__ ull    g_akey[NUM_A];  // per-anchor merged: (iou_bits<<32)|(~t)
__device__ ull    g_tkey[NUM_T];  // per-target merged: (iou_bits<<32)|(~anchor)
__device__ double g_cls_sum;
__device__ int    g_npos;

// ---------------- init -------------------------------------------------------
__global__ void init_kernel() {
    int i = blockIdx.x * 1024 + threadIdx.x;   // grid 96 x 1024 == NUM_A
    g_akey[i] = 0ULL;
    if (i < NUM_T) g_tkey[i] = 0ULL;
    if (i == 0) { g_cls_sum = 0.0; g_npos = 0; }
}

// ---------------- match: IoU argmax both sides, chunked ----------------------
__global__ void __launch_bounds__(BLK) match_kernel(
    const float* __restrict__ anchors,     // [A,4]
    const float* __restrict__ tboxes)      // [T,4]
{
    __shared__ float4 s_tb[CHUNK];
    __shared__ float  s_ta[CHUNK];

    const int tid   = threadIdx.x;
    const int tbase = blockIdx.y * CHUNK;

    if (tid < CHUNK) {
        float4 b = ((const float4*)tboxes)[tbase + tid];
        s_tb[tid] = b;
        s_ta[tid] = (b.z - b.x) * (b.w - b.y);
    }
    __syncthreads();

    const int a0 = blockIdx.x * (BLK * APT) + tid;
    const int a1 = a0 + BLK;
    const float4 ab0 = ((const float4*)anchors)[a0];
    const float4 ab1 = ((const float4*)anchors)[a1];
    const float area0 = (ab0.z - ab0.x) * (ab0.w - ab0.y);
    const float area1 = (ab1.z - ab1.x) * (ab1.w - ab1.y);

    float bi0 = 0.0f, bu0 = 1.0f, bi1 = 0.0f, bu1 = 1.0f;
    int   bt0 = 0, bt1 = 0;

    #pragma unroll 8
    for (int t = 0; t < CHUNK; ++t) {
        const float4 tb = s_tb[t];
        const float  ta = s_ta[t];

        // anchor 0
        {
            float lx = fmaxf(ab0.x, tb.x), ly = fmaxf(ab0.y, tb.y);
            float rx = fminf(ab0.z, tb.z), ry = fminf(ab0.w, tb.w);
            float w  = fmaxf(rx - lx, 0.0f);
            float h  = fmaxf(ry - ly, 0.0f);
            float inter = w * h;
            float uni   = (area0 + ta) - inter;
            bool p = inter * bu0 > bi0 * uni;     // strict > keeps first max
            bi0 = p ? inter : bi0;
            bu0 = p ? uni   : bu0;
            bt0 = p ? t     : bt0;
            if (inter > 0.45f * uni) {            // rare: target-side candidate
                float iou = __fdividef(inter, uni);
                ull key = ((ull)__float_as_uint(iou) << 32)
                        | (ull)(0xFFFFFFFFu - (unsigned)a0);
                atomicMax(&g_tkey[tbase + t], key);
            }
        }
        // anchor 1
        {
            float lx = fmaxf(ab1.x, tb.x), ly = fmaxf(ab1.y, tb.y);
            float rx = fminf(ab1.z, tb.z), ry = fminf(ab1.w, tb.w);
            float w  = fmaxf(rx - lx, 0.0f);
            float h  = fmaxf(ry - ly, 0.0f);
            float inter = w * h;
            float uni   = (area1 + ta) - inter;
            bool p = inter * bu1 > bi1 * uni;
            bi1 = p ? inter : bi1;
            bu1 = p ? uni   : bu1;
            bt1 = p ? t     : bt1;
            if (inter > 0.45f * uni) {
                float iou = __fdividef(inter, uni);
                ull key = ((ull)__float_as_uint(iou) << 32)
                        | (ull)(0xFFFFFFFFu - (unsigned)a1);
                atomicMax(&g_tkey[tbase + t], key);
            }
        }
    }

    // merge anchor-side partial best across chunks
    {
        float iou0 = __fdividef(bi0, bu0);
        ull k0 = ((ull)__float_as_uint(iou0) << 32)
               | (ull)(0xFFFFFFFFu - (unsigned)(tbase + bt0));
        atomicMax(&g_akey[a0], k0);
        float iou1 = __fdividef(bi1, bu1);
        ull k1 = ((ull)__float_as_uint(iou1) << 32)
               | (ull)(0xFFFFFFFFu - (unsigned)(tbase + bt1));
        atomicMax(&g_akey[a1], k1);
    }
}

// ---------------- classification focal loss ----------------------------------
__global__ void __launch_bounds__(256) focal_kernel(
    const float* __restrict__ cls_preds,   // [A,21]
    const int*   __restrict__ tlabels)     // [T]
{
    const int a = blockIdx.x * 256 + threadIdx.x;
    ull key = g_akey[a];
    float iou = __uint_as_float((unsigned)(key >> 32));
    bool  pos = iou >= 0.5f;
    int   t   = (int)(0xFFFFFFFFu - (unsigned)(key & 0xFFFFFFFFull));
    int   label = tlabels[t];

    float lsum = 0.0f;
    const float* lg = cls_preds + (size_t)a * NCLS;
    #pragma unroll
    for (int c = 0; c < NCLS; ++c) {
        float x = lg[c];
        bool  ypos = pos && (c == label);
        float ax = fabsf(x);
        float e  = expf(-ax);
        float ce = fmaxf(x, 0.0f) - (ypos ? x : 0.0f) + log1pf(e);
        float p  = 1.0f / (1.0f + expf(-x));
        float pt = ypos ? p : (1.0f - p);
        float at = ypos ? 0.25f : 0.75f;
        float om = 1.0f - pt;
        lsum += at * om * om * ce;
    }

    int np = pos ? 1 : 0;
    #pragma unroll
    for (int o = 16; o > 0; o >>= 1) {
        lsum += __shfl_down_sync(0xFFFFFFFFu, lsum, o);
        np   += __shfl_down_sync(0xFFFFFFFFu, np,   o);
    }
    __shared__ float rs[8];
    __shared__ int   ri[8];
    int lane = threadIdx.x & 31, wid = threadIdx.x >> 5;
    if (lane == 0) { rs[wid] = lsum; ri[wid] = np; }
    __syncthreads();
    if (threadIdx.x == 0) {
        float bs = 0.0f; int bn = 0;
        #pragma unroll
        for (int i = 0; i < 8; ++i) { bs += rs[i]; bn += ri[i]; }
        atomicAdd(&g_cls_sum, (double)bs);
        atomicAdd(&g_npos, bn);
    }
}

// ---------------- regression loss + final combine ----------------------------
__device__ __forceinline__ float sl1(float d) {
    float ad = fabsf(d);
    return (ad < 1.0f) ? 0.5f * d * d : ad - 0.5f;
}

__global__ void __launch_bounds__(1024) reg_final_kernel(
    const float* __restrict__ boxes_preds, // [A,4]
    const float* __restrict__ anchors,     // [A,4]
    const float* __restrict__ tboxes,      // [T,4]
    float* __restrict__ out)
{
    const int t = threadIdx.x;
    float loss = 0.0f;
    int   match = 0;

    ull key = g_tkey[t];
    float iou = __uint_as_float((unsigned)(key >> 32));
    if (iou >= 0.5f) {
        match = 1;
        unsigned aidx = 0xFFFFFFFFu - (unsigned)(key & 0xFFFFFFFFull);
        float4 ab = ((const float4*)anchors)[aidx];
        float4 tb = ((const float4*)tboxes)[t];
        float4 pr = ((const float4*)boxes_preds)[aidx];
        float bw = tb.z - tb.x, bh = tb.w - tb.y;
        float bcx = tb.x + 0.5f * bw, bcy = tb.y + 0.5f * bh;
        float aw = ab.z - ab.x, ah = ab.w - ab.y;
        float acx = ab.x + 0.5f * aw, acy = ab.y + 0.5f * ah;
        float tx = (bcx - acx) / aw;
        float ty = (bcy - acy) / ah;
        float tw = logf(fmaxf(bw, 1e-8f) / aw);
        float th = logf(fmaxf(bh, 1e-8f) / ah);
        loss = sl1(pr.x - tx) + sl1(pr.y - ty) + sl1(pr.z - tw) + sl1(pr.w - th);
    }

    #pragma unroll
    for (int o = 16; o > 0; o >>= 1) {
        loss  += __shfl_down_sync(0xFFFFFFFFu, loss,  o);
        match += __shfl_down_sync(0xFFFFFFFFu, match, o);
    }
    __shared__ float rs[32];
    __shared__ int   rm[32];
    int lane = t & 31, wid = t >> 5;
    if (lane == 0) { rs[wid] = loss; rm[wid] = match; }
    __syncthreads();
    if (t == 0) {
        double total = 0.0; int nm = 0;
        #pragma unroll
        for (int i = 0; i < 32; ++i) { total += (double)rs[i]; nm += rm[i]; }
        double n_match = (nm > 0) ? (double)nm : 1.0;
        double cls = g_cls_sum / (double)g_npos;
        double reg = total / (n_match * 4.0);
        out[0] = (float)(cls + reg);
        out[1] = (float)cls;
        out[2] = (float)reg;
    }
}

// ---------------- launch -----------------------------------------------------
extern "C" void kernel_launch(void* const* d_in, const int* in_sizes, int n_in,
                              void* d_out, int out_size) {
    const float* cls_preds = (const float*)d_in[0];
    const float* box_preds = (const float*)d_in[1];
    const float* anchors   = (const float*)d_in[2];
    const float* tboxes    = (const float*)d_in[3];
    const int*   tlabels   = (const int*)d_in[4];
    float* out = (float*)d_out;

    init_kernel<<<NUM_A / 1024, 1024>>>();
    dim3 mg(NUM_A / (BLK * APT), NCHUNK);
    match_kernel<<<mg, BLK>>>(anchors, tboxes);
    focal_kernel<<<NUM_A / 256, 256>>>(cls_preds, tlabels);
    reg_final_kernel<<<1, 1024>>>(box_preds, anchors, tboxes, out);
}

// round 3
// speedup vs baseline: 1.3669x; 1.0995x over previous
#include <cuda_runtime.h>
#include <cstdint>

#define NUM_A   98304
#define NUM_T   1024
#define NCLS    21
#define NLOGIT  (NUM_A * NCLS)     // 2064384
#define NVEC    (NLOGIT / 4)       // 516096 float4s

#define CHUNK   128
#define NCHUNK  8
#define APT     4
#define BLK     128
#define AG      (NUM_A / (BLK * APT))   // 192 anchor groups
#define MATCH_BLOCKS (AG * NCHUNK)      // 1536
#define FOCAL_BLOCKS 768
#define FOCAL_THREADS (FOCAL_BLOCKS * BLK)  // 98304

typedef unsigned long long ull;

// ---------------- device-global scratch --------------------------------------
__device__ ull    g_akey[NUM_A];  // per-anchor: (iou_bits<<32)|(~t)
__device__ ull    g_tkey[NUM_T];  // per-target: (iou_bits<<32)|(~anchor)
__device__ double g_cls_sum;
__device__ int    g_npos;

// fast negative-class focal: 0.75 * sigmoid(x)^2 * softplus(x) ; 3 MUFU ops
__device__ __forceinline__ float focal_neg(float x) {
    float u = exp2f(x * 1.4426950408889634f);   // e^x   (EX2)
    float d = u + 1.0f;
    float q; asm("rcp.approx.f32 %0, %1;" : "=f"(q) : "f"(d));  // 1/(1+e^x)
    float lg = __log2f(d);                      // log2(1+e^x)  (LG2)
    float p  = u * q;                           // sigmoid(x)
    return (0.75f * 0.6931471805599453f) * (p * p) * lg;
}

// ---------------- init -------------------------------------------------------
__global__ void init_kernel() {
    int i = blockIdx.x * 1024 + threadIdx.x;   // 96 x 1024 == NUM_A
    g_akey[i] = 0ULL;
    if (i < NUM_T) g_tkey[i] = 0ULL;
    if (i == 0) { g_cls_sum = 0.0; g_npos = 0; }
}

// ---------------- fused: match blocks + neg-focal blocks ---------------------
__global__ void __launch_bounds__(BLK) fused_kernel(
    const float* __restrict__ anchors,     // [A,4]
    const float* __restrict__ tboxes,      // [T,4]
    const float* __restrict__ cls_preds)   // [A,21] (flat for focal)
{
    const int tid = threadIdx.x;

    if (blockIdx.x >= MATCH_BLOCKS) {
        // ---- negative-focal over the whole logit array (match-independent) --
        const int gt = (blockIdx.x - MATCH_BLOCKS) * BLK + tid;
        const float4* cp = (const float4*)cls_preds;
        float acc = 0.0f;
        for (int i = gt; i < NVEC; i += FOCAL_THREADS) {
            float4 v = cp[i];
            acc += focal_neg(v.x) + focal_neg(v.y)
                 + focal_neg(v.z) + focal_neg(v.w);
        }
        #pragma unroll
        for (int o = 16; o > 0; o >>= 1)
            acc += __shfl_down_sync(0xFFFFFFFFu, acc, o);
        __shared__ float rs[4];
        if ((tid & 31) == 0) rs[tid >> 5] = acc;
        __syncthreads();
        if (tid == 0)
            atomicAdd(&g_cls_sum, (double)(rs[0] + rs[1] + rs[2] + rs[3]));
        return;
    }

    // ---- match: IoU argmax both sides, chunked ------------------------------
    __shared__ float4 s_tb[CHUNK];
    __shared__ float  s_ta[CHUNK];

    const int g     = blockIdx.x % AG;
    const int tbase = (blockIdx.x / AG) * CHUNK;

    {
        float4 b = ((const float4*)tboxes)[tbase + tid];   // BLK == CHUNK
        s_tb[tid] = b;
        s_ta[tid] = (b.z - b.x) * (b.w - b.y);
    }
    __syncthreads();

    const int a0 = g * (BLK * APT) + tid;
    float4 A[APT]; float area[APT], bi[APT], bS[APT]; int bt[APT];
    #pragma unroll
    for (int k = 0; k < APT; ++k) {
        A[k]    = ((const float4*)anchors)[a0 + k * BLK];
        area[k] = (A[k].z - A[k].x) * (A[k].w - A[k].y);
        bi[k] = 0.0f; bS[k] = 1.0f; bt[k] = 0;
    }

    #pragma unroll 4
    for (int t = 0; t < CHUNK; ++t) {
        const float4 tb = s_tb[t];
        const float  ta = s_ta[t];
        #pragma unroll
        for (int k = 0; k < APT; ++k) {
            float lx = fmaxf(A[k].x, tb.x);
            float ly = fmaxf(A[k].y, tb.y);
            float rx = fminf(A[k].z, tb.z);
            float ry = fminf(A[k].w, tb.w);
            float w  = fmaxf(rx - lx, 0.0f);
            float h  = ry - ly;                 // no clamp: neg inter loses all tests
            float inter = w * h;
            float S     = area[k] + ta;         // union == S - inter (implicit)
            // iou_new > iou_best  <=>  inter*bS > bi*S   (cross terms cancel)
            bool p = inter * bS[k] > bi[k] * S;
            bi[k] = p ? inter : bi[k];
            bS[k] = p ? S     : bS[k];
            bt[k] = p ? t     : bt[k];
            // target-side candidate: iou > 0.45  <=>  inter > 0.45/1.45 * S
            if (inter > 0.3103448f * S) {
                float iou = __fdividef(inter, S - inter);
                ull key = ((ull)__float_as_uint(iou) << 32)
                        | (ull)(0xFFFFFFFFu - (unsigned)(a0 + k * BLK));
                atomicMax(&g_tkey[tbase + t], key);
            }
        }
    }

    #pragma unroll
    for (int k = 0; k < APT; ++k) {
        float iou = __fdividef(bi[k], bS[k] - bi[k]);
        ull key = ((ull)__float_as_uint(iou) << 32)
                | (ull)(0xFFFFFFFFu - (unsigned)(tbase + bt[k]));
        atomicMax(&g_akey[a0 + k * BLK], key);
    }
}

// ---------------- epilogue: pos-anchor focal correction + n_pos --------------
__global__ void __launch_bounds__(256) epilogue_kernel(
    const float* __restrict__ cls_preds,
    const int*   __restrict__ tlabels)
{
    const int a = blockIdx.x * 256 + threadIdx.x;
    ull key = g_akey[a];
    float iou = __uint_as_float((unsigned)(key >> 32));
    float delta = 0.0f;
    int   np = 0;
    if (iou >= 0.5f) {
        np = 1;
        int t = (int)(0xFFFFFFFFu - (unsigned)(key & 0xFFFFFFFFull));
        int L = tlabels[t];
        float x = cls_preds[(size_t)a * NCLS + L];
        // accurate positive-class focal (matches reference formula)
        float ax = fabsf(x);
        float ce = fmaxf(x, 0.0f) - x + log1pf(expf(-ax));
        float p  = 1.0f / (1.0f + expf(-x));
        float om = 1.0f - p;
        float fpos = 0.25f * om * om * ce;
        delta = fpos - focal_neg(x);   // cancel what the neg pass added
    }
    #pragma unroll
    for (int o = 16; o > 0; o >>= 1) {
        delta += __shfl_down_sync(0xFFFFFFFFu, delta, o);
        np    += __shfl_down_sync(0xFFFFFFFFu, np,    o);
    }
    __shared__ float rs[8];
    __shared__ int   ri[8];
    int lane = threadIdx.x & 31, wid = threadIdx.x >> 5;
    if (lane == 0) { rs[wid] = delta; ri[wid] = np; }
    __syncthreads();
    if (threadIdx.x == 0) {
        float bs = 0.0f; int bn = 0;
        #pragma unroll
        for (int i = 0; i < 8; ++i) { bs += rs[i]; bn += ri[i]; }
        atomicAdd(&g_cls_sum, (double)bs);
        atomicAdd(&g_npos, bn);
    }
}

// ---------------- regression loss + final combine ----------------------------
__device__ __forceinline__ float sl1(float d) {
    float ad = fabsf(d);
    return (ad < 1.0f) ? 0.5f * d * d : ad - 0.5f;
}

__global__ void __launch_bounds__(1024) final_kernel(
    const float* __restrict__ boxes_preds,
    const float* __restrict__ anchors,
    const float* __restrict__ tboxes,
    float* __restrict__ out)
{
    const int t = threadIdx.x;
    float loss = 0.0f;
    int   match = 0;

    ull key = g_tkey[t];
    float iou = __uint_as_float((unsigned)(key >> 32));
    if (iou >= 0.5f) {
        match = 1;
        unsigned aidx = 0xFFFFFFFFu - (unsigned)(key & 0xFFFFFFFFull);
        float4 ab = ((const float4*)anchors)[aidx];
        float4 tb = ((const float4*)tboxes)[t];
        float4 pr = ((const float4*)boxes_preds)[aidx];
        float bw = tb.z - tb.x, bh = tb.w - tb.y;
        float bcx = tb.x + 0.5f * bw, bcy = tb.y + 0.5f * bh;
        float aw = ab.z - ab.x, ah = ab.w - ab.y;
        float acx = ab.x + 0.5f * aw, acy = ab.y + 0.5f * ah;
        float tx = (bcx - acx) / aw;
        float ty = (bcy - acy) / ah;
        float tw = logf(fmaxf(bw, 1e-8f) / aw);
        float th = logf(fmaxf(bh, 1e-8f) / ah);
        loss = sl1(pr.x - tx) + sl1(pr.y - ty) + sl1(pr.z - tw) + sl1(pr.w - th);
    }

    #pragma unroll
    for (int o = 16; o > 0; o >>= 1) {
        loss  += __shfl_down_sync(0xFFFFFFFFu, loss,  o);
        match += __shfl_down_sync(0xFFFFFFFFu, match, o);
    }
    __shared__ float rs[32];
    __shared__ int   rm[32];
    int lane = t & 31, wid = t >> 5;
    if (lane == 0) { rs[wid] = loss; rm[wid] = match; }
    __syncthreads();
    if (t == 0) {
        double total = 0.0; int nm = 0;
        #pragma unroll
        for (int i = 0; i < 32; ++i) { total += (double)rs[i]; nm += rm[i]; }
        double n_match = (nm > 0) ? (double)nm : 1.0;
        double cls = g_cls_sum / (double)g_npos;
        double reg = total / (n_match * 4.0);
        out[0] = (float)(cls + reg);
        out[1] = (float)cls;
        out[2] = (float)reg;
    }
}

// ---------------- launch -----------------------------------------------------
extern "C" void kernel_launch(void* const* d_in, const int* in_sizes, int n_in,
                              void* d_out, int out_size) {
    const float* cls_preds = (const float*)d_in[0];
    const float* box_preds = (const float*)d_in[1];
    const float* anchors   = (const float*)d_in[2];
    const float* tboxes    = (const float*)d_in[3];
    const int*   tlabels   = (const int*)d_in[4];
    float* out = (float*)d_out;

    init_kernel<<<NUM_A / 1024, 1024>>>();
    fused_kernel<<<MATCH_BLOCKS + FOCAL_BLOCKS, BLK>>>(anchors, tboxes, cls_preds);
    epilogue_kernel<<<NUM_A / 256, 256>>>(cls_preds, tlabels);
    final_kernel<<<1, 1024>>>(box_preds, anchors, tboxes, out);
}